// round 2
// baseline (speedup 1.0000x reference)
#include <cuda_runtime.h>
#include <math.h>

#define Bz 4
#define Cc 256
#define Nn 4096

// Scratch (device globals — no allocation allowed in kernel_launch)
__device__ float g_Q[Bz * Cc * Nn];
__device__ float g_K[Bz * Cc * Nn];
__device__ float g_V[Bz * Cc * Nn];
__device__ float g_S[(size_t)Bz * Nn * Nn];  // 256 MB scores / probs

#define BK 16
#define LD 132   // 128 + 4 pad; 132*4 bytes = 528, divisible by 16 -> float4-safe rows

// ---------------------------------------------------------------------------
// Kernel 1: QKV projection.  Y[o,n] = sum_c W[o,c] * X[c,n] + bias[o]
// grid: (N/128, C/128, B*3), block 256
// ---------------------------------------------------------------------------
__global__ __launch_bounds__(256) void qkv_kernel(
    const float* __restrict__ x,
    const float* __restrict__ Wq, const float* __restrict__ bq,
    const float* __restrict__ Wk, const float* __restrict__ bk,
    const float* __restrict__ Wv, const float* __restrict__ bv)
{
    int m = blockIdx.z % 3;
    int b = blockIdx.z / 3;
    const float* W    = (m == 0) ? Wq : (m == 1) ? Wk : Wv;
    const float* bias = (m == 0) ? bq : (m == 1) ? bk : bv;
    float* Y = ((m == 0) ? g_Q : (m == 1) ? g_K : g_V) + (size_t)b * Cc * Nn;
    const float* X = x + (size_t)b * Cc * Nn;

    int o0 = blockIdx.y * 128;
    int n0 = blockIdx.x * 128;

    __shared__ float As[BK][LD];  // As[k][o]   (W transposed in)
    __shared__ float Bs[BK][LD];  // Bs[k][n]

    int tid = threadIdx.x;
    int tx = tid & 15, ty = tid >> 4;
    float acc[8][8] = {};

    for (int k0 = 0; k0 < Cc; k0 += BK) {
        // W tile [128 o][16 c] -> transpose-store
        #pragma unroll
        for (int it = 0; it < 2; ++it) {
            int idx = tid + it * 256;       // 0..511
            int o  = idx >> 2;              // 0..127
            int k4 = idx & 3;
            float4 v = *(const float4*)&W[(o0 + o) * Cc + k0 + k4 * 4];
            As[k4 * 4 + 0][o] = v.x; As[k4 * 4 + 1][o] = v.y;
            As[k4 * 4 + 2][o] = v.z; As[k4 * 4 + 3][o] = v.w;
        }
        // X tile [16 c][128 n] -> direct
        #pragma unroll
        for (int it = 0; it < 2; ++it) {
            int idx = tid + it * 256;
            int k  = idx >> 5;              // 0..15
            int n4 = idx & 31;
            *(float4*)&Bs[k][n4 * 4] =
                *(const float4*)&X[(k0 + k) * Nn + n0 + n4 * 4];
        }
        __syncthreads();
        #pragma unroll
        for (int k = 0; k < BK; ++k) {
            float a[8], bb[8];
            *(float4*)&a[0]  = *(const float4*)&As[k][ty * 8];
            *(float4*)&a[4]  = *(const float4*)&As[k][ty * 8 + 4];
            *(float4*)&bb[0] = *(const float4*)&Bs[k][tx * 8];
            *(float4*)&bb[4] = *(const float4*)&Bs[k][tx * 8 + 4];
            #pragma unroll
            for (int r = 0; r < 8; ++r)
                #pragma unroll
                for (int c = 0; c < 8; ++c)
                    acc[r][c] += a[r] * bb[c];
        }
        __syncthreads();
    }

    #pragma unroll
    for (int r = 0; r < 8; ++r) {
        int o = o0 + ty * 8 + r;
        float bvv = bias[o];
        float4 s0, s1;
        s0.x = acc[r][0] + bvv; s0.y = acc[r][1] + bvv;
        s0.z = acc[r][2] + bvv; s0.w = acc[r][3] + bvv;
        s1.x = acc[r][4] + bvv; s1.y = acc[r][5] + bvv;
        s1.z = acc[r][6] + bvv; s1.w = acc[r][7] + bvv;
        *(float4*)&Y[(size_t)o * Nn + n0 + tx * 8]     = s0;
        *(float4*)&Y[(size_t)o * Nn + n0 + tx * 8 + 4] = s1;
    }
}

// ---------------------------------------------------------------------------
// Kernel 2: scores S[i,j] = (1/16) sum_c Q[c,i] K[c,j]
// grid: (N/128 j, N/128 i, B), block 256
// ---------------------------------------------------------------------------
__global__ __launch_bounds__(256) void scores_kernel()
{
    int b = blockIdx.z;
    const float* Q = g_Q + (size_t)b * Cc * Nn;
    const float* K = g_K + (size_t)b * Cc * Nn;
    float* S = g_S + (size_t)b * Nn * Nn;

    int i0 = blockIdx.y * 128;
    int j0 = blockIdx.x * 128;

    __shared__ float As[BK][LD];  // As[k][i]
    __shared__ float Bs[BK][LD];  // Bs[k][j]

    int tid = threadIdx.x;
    int tx = tid & 15, ty = tid >> 4;
    float acc[8][8] = {};

    for (int k0 = 0; k0 < Cc; k0 += BK) {
        // both operands: contiguous along i/j, k along c -> direct loads
        #pragma unroll
        for (int it = 0; it < 2; ++it) {
            int idx = tid + it * 256;
            int k  = idx >> 5;
            int n4 = idx & 31;
            *(float4*)&As[k][n4 * 4] =
                *(const float4*)&Q[(k0 + k) * Nn + i0 + n4 * 4];
            *(float4*)&Bs[k][n4 * 4] =
                *(const float4*)&K[(k0 + k) * Nn + j0 + n4 * 4];
        }
        __syncthreads();
        #pragma unroll
        for (int k = 0; k < BK; ++k) {
            float a[8], bb[8];
            *(float4*)&a[0]  = *(const float4*)&As[k][ty * 8];
            *(float4*)&a[4]  = *(const float4*)&As[k][ty * 8 + 4];
            *(float4*)&bb[0] = *(const float4*)&Bs[k][tx * 8];
            *(float4*)&bb[4] = *(const float4*)&Bs[k][tx * 8 + 4];
            #pragma unroll
            for (int r = 0; r < 8; ++r)
                #pragma unroll
                for (int c = 0; c < 8; ++c)
                    acc[r][c] += a[r] * bb[c];
        }
        __syncthreads();
    }

    const float scale = 0.0625f;  // 1/sqrt(256)
    #pragma unroll
    for (int r = 0; r < 8; ++r) {
        size_t base = (size_t)(i0 + ty * 8 + r) * Nn + j0 + tx * 8;
        float4 s0, s1;
        s0.x = acc[r][0] * scale; s0.y = acc[r][1] * scale;
        s0.z = acc[r][2] * scale; s0.w = acc[r][3] * scale;
        s1.x = acc[r][4] * scale; s1.y = acc[r][5] * scale;
        s1.z = acc[r][6] * scale; s1.w = acc[r][7] * scale;
        *(float4*)&S[base]     = s0;
        *(float4*)&S[base + 4] = s1;
    }
}

// ---------------------------------------------------------------------------
// Kernel 3: row softmax over j. grid: (N, B), block 256 (16 elems/thread)
// ---------------------------------------------------------------------------
__device__ __forceinline__ float warp_max(float v) {
    #pragma unroll
    for (int o = 16; o > 0; o >>= 1)
        v = fmaxf(v, __shfl_xor_sync(0xffffffffu, v, o));
    return v;
}
__device__ __forceinline__ float warp_sum(float v) {
    #pragma unroll
    for (int o = 16; o > 0; o >>= 1)
        v += __shfl_xor_sync(0xffffffffu, v, o);
    return v;
}

__global__ __launch_bounds__(256) void softmax_kernel()
{
    int i = blockIdx.x, b = blockIdx.y;
    float* row = g_S + ((size_t)b * Nn + i) * Nn;
    int tid = threadIdx.x;
    int lane = tid & 31, w = tid >> 5;

    float4 v[4];
    float mx = -1e30f;
    #pragma unroll
    for (int c = 0; c < 4; ++c) {
        v[c] = *(const float4*)&row[(c * 256 + tid) * 4];
        mx = fmaxf(mx, fmaxf(fmaxf(v[c].x, v[c].y), fmaxf(v[c].z, v[c].w)));
    }

    __shared__ float redm[8], reds[8];
    mx = warp_max(mx);
    if (lane == 0) redm[w] = mx;
    __syncthreads();
    float m = redm[0];
    #pragma unroll
    for (int k = 1; k < 8; ++k) m = fmaxf(m, redm[k]);

    float s = 0.f;
    #pragma unroll
    for (int c = 0; c < 4; ++c) {
        v[c].x = __expf(v[c].x - m); v[c].y = __expf(v[c].y - m);
        v[c].z = __expf(v[c].z - m); v[c].w = __expf(v[c].w - m);
        s += v[c].x + v[c].y + v[c].z + v[c].w;
    }
    s = warp_sum(s);
    if (lane == 0) reds[w] = s;
    __syncthreads();
    float tot = 0.f;
    #pragma unroll
    for (int k = 0; k < 8; ++k) tot += reds[k];
    float inv = __frcp_rn(tot);

    #pragma unroll
    for (int c = 0; c < 4; ++c) {
        v[c].x *= inv; v[c].y *= inv; v[c].z *= inv; v[c].w *= inv;
        *(float4*)&row[(c * 256 + tid) * 4] = v[c];
    }
}

// ---------------------------------------------------------------------------
// Kernel 4: context + residual. out[c,i] = x[c,i] + sum_j V[c,j] P[i,j]
// grid: (N/128 i, C/128 c, B), block 256
// ---------------------------------------------------------------------------
__global__ __launch_bounds__(256) void context_kernel(
    const float* __restrict__ x, float* __restrict__ out)
{
    int b = blockIdx.z;
    const float* V = g_V + (size_t)b * Cc * Nn;
    const float* P = g_S + (size_t)b * Nn * Nn;

    int c0 = blockIdx.y * 128;
    int i0 = blockIdx.x * 128;

    __shared__ float As[BK][LD];  // As[kj][c]
    __shared__ float Bs[BK][LD];  // Bs[kj][i]

    int tid = threadIdx.x;
    int tx = tid & 15, ty = tid >> 4;
    float acc[8][8] = {};

    for (int j0 = 0; j0 < Nn; j0 += BK) {
        // V tile [128 c][16 j] -> transpose-store
        // P tile [128 i][16 j] -> transpose-store
        #pragma unroll
        for (int it = 0; it < 2; ++it) {
            int idx = tid + it * 256;
            int r  = idx >> 2;          // 0..127
            int k4 = idx & 3;
            float4 va = *(const float4*)&V[(c0 + r) * Nn + j0 + k4 * 4];
            As[k4 * 4 + 0][r] = va.x; As[k4 * 4 + 1][r] = va.y;
            As[k4 * 4 + 2][r] = va.z; As[k4 * 4 + 3][r] = va.w;
            float4 vb = *(const float4*)&P[(size_t)(i0 + r) * Nn + j0 + k4 * 4];
            Bs[k4 * 4 + 0][r] = vb.x; Bs[k4 * 4 + 1][r] = vb.y;
            Bs[k4 * 4 + 2][r] = vb.z; Bs[k4 * 4 + 3][r] = vb.w;
        }
        __syncthreads();
        #pragma unroll
        for (int k = 0; k < BK; ++k) {
            float a[8], bb[8];
            *(float4*)&a[0]  = *(const float4*)&As[k][ty * 8];
            *(float4*)&a[4]  = *(const float4*)&As[k][ty * 8 + 4];
            *(float4*)&bb[0] = *(const float4*)&Bs[k][tx * 8];
            *(float4*)&bb[4] = *(const float4*)&Bs[k][tx * 8 + 4];
            #pragma unroll
            for (int r = 0; r < 8; ++r)
                #pragma unroll
                for (int c = 0; c < 8; ++c)
                    acc[r][c] += a[r] * bb[c];
        }
        __syncthreads();
    }

    #pragma unroll
    for (int r = 0; r < 8; ++r) {
        size_t base = ((size_t)b * Cc + c0 + ty * 8 + r) * Nn + i0 + tx * 8;
        float4 x0 = *(const float4*)&x[base];
        float4 x1 = *(const float4*)&x[base + 4];
        float4 s0, s1;
        s0.x = acc[r][0] + x0.x; s0.y = acc[r][1] + x0.y;
        s0.z = acc[r][2] + x0.z; s0.w = acc[r][3] + x0.w;
        s1.x = acc[r][4] + x1.x; s1.y = acc[r][5] + x1.y;
        s1.z = acc[r][6] + x1.z; s1.w = acc[r][7] + x1.w;
        *(float4*)&out[base]     = s0;
        *(float4*)&out[base + 4] = s1;
    }
}

// ---------------------------------------------------------------------------
extern "C" void kernel_launch(void* const* d_in, const int* in_sizes, int n_in,
                              void* d_out, int out_size)
{
    const float* x  = (const float*)d_in[0];
    const float* Wq = (const float*)d_in[1];
    const float* bq = (const float*)d_in[2];
    const float* Wk = (const float*)d_in[3];
    const float* bk = (const float*)d_in[4];
    const float* Wv = (const float*)d_in[5];
    const float* bv = (const float*)d_in[6];
    float* out = (float*)d_out;

    dim3 blk(256);

    dim3 g_qkv(Nn / 128, Cc / 128, Bz * 3);       // 32, 2, 12
    qkv_kernel<<<g_qkv, blk>>>(x, Wq, bq, Wk, bk, Wv, bv);

    dim3 g_sc(Nn / 128, Nn / 128, Bz);            // 32, 32, 4
    scores_kernel<<<g_sc, blk>>>();

    dim3 g_sm(Nn, Bz);                            // 4096, 4
    softmax_kernel<<<g_sm, blk>>>();

    dim3 g_ctx(Nn / 128, Cc / 128, Bz);           // 32, 2, 4
    context_kernel<<<g_ctx, blk>>>(x, out);
}

// round 4
// speedup vs baseline: 4.0668x; 4.0668x over previous
#include <cuda_runtime.h>
#include <cuda_bf16.h>
#include <cstdint>
#include <math.h>

#define Bz 4
#define Cc 256
#define Nn 4096

// ---------------- device scratch (no allocation allowed) --------------------
__device__ __nv_bfloat16 g_Qt[(size_t)Bz * Nn * Cc];  // Q^T  [b][i][c]
__device__ __nv_bfloat16 g_Kt[(size_t)Bz * Nn * Cc];  // K^T  [b][j][c]
__device__ __nv_bfloat16 g_Vb[(size_t)Bz * Cc * Nn];  // V    [b][c][j]
__device__ float         g_S [(size_t)Bz * Nn * Nn];  // scores fp32
__device__ __nv_bfloat16 g_P [(size_t)Bz * Nn * Nn];  // probs bf16 [b][i][j]

// ---------------- PTX helpers (all valid on plain sm_103 target) ------------
__device__ __forceinline__ uint32_t smem_u32(const void* p) {
    uint32_t a;
    asm("{ .reg .u64 t; cvta.to.shared.u64 t, %1; cvt.u32.u64 %0, t; }"
        : "=r"(a) : "l"(p));
    return a;
}
__device__ __forceinline__ void ldsm4(uint32_t* r, uint32_t a) {
    asm volatile("ldmatrix.sync.aligned.m8n8.x4.shared.b16 {%0,%1,%2,%3}, [%4];"
                 : "=r"(r[0]), "=r"(r[1]), "=r"(r[2]), "=r"(r[3]) : "r"(a));
}
__device__ __forceinline__ void mma16816(float* c, const uint32_t* a,
                                         uint32_t b0, uint32_t b1) {
    asm volatile(
        "mma.sync.aligned.m16n8k16.row.col.f32.bf16.bf16.f32 "
        "{%0,%1,%2,%3}, {%4,%5,%6,%7}, {%8,%9}, {%0,%1,%2,%3};"
        : "+f"(c[0]), "+f"(c[1]), "+f"(c[2]), "+f"(c[3])
        : "r"(a[0]), "r"(a[1]), "r"(a[2]), "r"(a[3]), "r"(b0), "r"(b1));
}
#define CP_ASYNC16(dst, src) \
    asm volatile("cp.async.cg.shared.global [%0], [%1], 16;" :: "r"(dst), "l"(src))
#define CP_COMMIT() asm volatile("cp.async.commit_group;" ::: "memory")

#define LDS 40  // bf16 elems per smem row: 80B stride -> 16B aligned, conflict-free

// ---------------------------------------------------------------------------
// Shared mma-GEMM core: C[128m x 128n] += A[128m x K] * B[128n x K]^T
// A rows stride LDGA, B rows stride LDGB (both K-major), K = KT*32.
// block 256 (8 warps), warp tile 64x32.
// ---------------------------------------------------------------------------
template<int LDGA, int LDGB, int KT>
__device__ __forceinline__ void gemm_bf16(
    const __nv_bfloat16* __restrict__ Ag,
    const __nv_bfloat16* __restrict__ Bg,
    float acc[4][4][4])
{
    __shared__ alignas(16) __nv_bfloat16 Asm[2][128 * LDS];
    __shared__ alignas(16) __nv_bfloat16 Bsm[2][128 * LDS];

    const int tid = threadIdx.x;
    const int lane = tid & 31, wid = tid >> 5;
    const int wm = wid & 1, wn = wid >> 1;

    // per-thread cp.async mapping: 512 chunks of 16B per operand per stage
    const int r0 = tid >> 2, cb = tid & 3;

    auto load_tile = [&](int s, int kt) {
        int k0 = kt * 32;
        #pragma unroll
        for (int h = 0; h < 2; ++h) {
            int r = r0 + h * 64;
            uint32_t da = smem_u32(&Asm[s][r * LDS + cb * 8]);
            CP_ASYNC16(da, Ag + (size_t)r * LDGA + k0 + cb * 8);
            uint32_t db = smem_u32(&Bsm[s][r * LDS + cb * 8]);
            CP_ASYNC16(db, Bg + (size_t)r * LDGB + k0 + cb * 8);
        }
        CP_COMMIT();
    };

    // precomputed ldmatrix lane addressing
    const int a_row = wm * 64 + (lane & 15);
    const int a_koff = (lane >> 4) * 8;
    const int b_row = wn * 32 + (lane & 7) + ((lane >> 4) << 3);
    const int b_koff = ((lane >> 3) & 1) * 8;

    load_tile(0, 0);

    #pragma unroll 1
    for (int kt = 0; kt < KT; ++kt) {
        if (kt + 1 < KT) {
            load_tile((kt + 1) & 1, kt + 1);
            asm volatile("cp.async.wait_group 1;" ::: "memory");
        } else {
            asm volatile("cp.async.wait_group 0;" ::: "memory");
        }
        __syncthreads();

        const __nv_bfloat16* as = &Asm[kt & 1][0];
        const __nv_bfloat16* bs = &Bsm[kt & 1][0];

        #pragma unroll
        for (int ks = 0; ks < 2; ++ks) {
            int k0 = ks * 16;
            uint32_t af[4][4], bf[2][4];
            #pragma unroll
            for (int mi = 0; mi < 4; ++mi)
                ldsm4(af[mi], smem_u32(as + (a_row + mi * 16) * LDS + k0 + a_koff));
            #pragma unroll
            for (int nh = 0; nh < 2; ++nh)
                ldsm4(bf[nh], smem_u32(bs + (b_row + nh * 16) * LDS + k0 + b_koff));
            #pragma unroll
            for (int mi = 0; mi < 4; ++mi)
                #pragma unroll
                for (int ni = 0; ni < 4; ++ni)
                    mma16816(acc[mi][ni], af[mi],
                             bf[ni >> 1][(ni & 1) * 2], bf[ni >> 1][(ni & 1) * 2 + 1]);
        }
        __syncthreads();
    }
}

// ---------------------------------------------------------------------------
// Kernel 1: QKV projection (fp32 SIMT) -> bf16 operand layouts
// ---------------------------------------------------------------------------
#define BK 16
#define LDA 132

__global__ __launch_bounds__(256) void qkv_kernel(
    const float* __restrict__ x,
    const float* __restrict__ Wq, const float* __restrict__ bq,
    const float* __restrict__ Wk, const float* __restrict__ bk,
    const float* __restrict__ Wv, const float* __restrict__ bv)
{
    int m = blockIdx.z % 3;
    int b = blockIdx.z / 3;
    const float* W    = (m == 0) ? Wq : (m == 1) ? Wk : Wv;
    const float* bias = (m == 0) ? bq : (m == 1) ? bk : bv;
    const float* X = x + (size_t)b * Cc * Nn;

    int o0 = blockIdx.y * 128;
    int n0 = blockIdx.x * 128;

    __shared__ float As[BK][LDA];
    __shared__ float Bs[BK][LDA];

    int tid = threadIdx.x;
    int tx = tid & 15, ty = tid >> 4;
    float acc[8][8] = {};

    for (int k0 = 0; k0 < Cc; k0 += BK) {
        #pragma unroll
        for (int it = 0; it < 2; ++it) {
            int idx = tid + it * 256;
            int o = idx >> 2, k4 = idx & 3;
            float4 v = *(const float4*)&W[(o0 + o) * Cc + k0 + k4 * 4];
            As[k4 * 4 + 0][o] = v.x; As[k4 * 4 + 1][o] = v.y;
            As[k4 * 4 + 2][o] = v.z; As[k4 * 4 + 3][o] = v.w;
        }
        #pragma unroll
        for (int it = 0; it < 2; ++it) {
            int idx = tid + it * 256;
            int k = idx >> 5, n4 = idx & 31;
            *(float4*)&Bs[k][n4 * 4] = *(const float4*)&X[(k0 + k) * Nn + n0 + n4 * 4];
        }
        __syncthreads();
        #pragma unroll
        for (int k = 0; k < BK; ++k) {
            float a[8], bb[8];
            *(float4*)&a[0]  = *(const float4*)&As[k][ty * 8];
            *(float4*)&a[4]  = *(const float4*)&As[k][ty * 8 + 4];
            *(float4*)&bb[0] = *(const float4*)&Bs[k][tx * 8];
            *(float4*)&bb[4] = *(const float4*)&Bs[k][tx * 8 + 4];
            #pragma unroll
            for (int r = 0; r < 8; ++r)
                #pragma unroll
                for (int c = 0; c < 8; ++c)
                    acc[r][c] += a[r] * bb[c];
        }
        __syncthreads();
    }

    float bias8[8];
    #pragma unroll
    for (int r = 0; r < 8; ++r) bias8[r] = bias[o0 + ty * 8 + r];

    if (m == 2) {
        __nv_bfloat16* Vb = g_Vb + (size_t)b * Cc * Nn;
        #pragma unroll
        for (int r = 0; r < 8; ++r) {
            __nv_bfloat162 p[4];
            #pragma unroll
            for (int e = 0; e < 4; ++e)
                p[e] = __floats2bfloat162_rn(acc[r][2 * e] + bias8[r],
                                             acc[r][2 * e + 1] + bias8[r]);
            *(uint4*)&Vb[(size_t)(o0 + ty * 8 + r) * Nn + n0 + tx * 8] = *(uint4*)p;
        }
    } else {
        __nv_bfloat16* T = ((m == 0) ? g_Qt : g_Kt) + (size_t)b * Nn * Cc;
        #pragma unroll
        for (int c = 0; c < 8; ++c) {
            __nv_bfloat162 p[4];
            #pragma unroll
            for (int e = 0; e < 4; ++e)
                p[e] = __floats2bfloat162_rn(acc[2 * e][c] + bias8[2 * e],
                                             acc[2 * e + 1][c] + bias8[2 * e + 1]);
            *(uint4*)&T[(size_t)(n0 + tx * 8 + c) * Cc + o0 + ty * 8] = *(uint4*)p;
        }
    }
}

// ---------------------------------------------------------------------------
// Kernel 2: scores via HMMA. S[i,j] = (1/16) sum_c Qt[i,c] Kt[j,c]
// grid: (N/128 j, N/128 i, B), block 256
// ---------------------------------------------------------------------------
__global__ __launch_bounds__(256) void scores_mma()
{
    int b = blockIdx.z;
    int i0 = blockIdx.y * 128, j0 = blockIdx.x * 128;
    const __nv_bfloat16* A  = g_Qt + (size_t)b * Nn * Cc + (size_t)i0 * Cc;
    const __nv_bfloat16* Bg = g_Kt + (size_t)b * Nn * Cc + (size_t)j0 * Cc;
    float* S = g_S + (size_t)b * Nn * Nn;

    float acc[4][4][4] = {};
    gemm_bf16<Cc, Cc, Cc / 32>(A, Bg, acc);

    int lane = threadIdx.x & 31, wid = threadIdx.x >> 5;
    int wm = wid & 1, wn = wid >> 1;
    const float sc = 0.0625f;

    #pragma unroll
    for (int mi = 0; mi < 4; ++mi) {
        int rb = i0 + wm * 64 + mi * 16 + (lane >> 2);
        #pragma unroll
        for (int ni = 0; ni < 4; ++ni) {
            int col = j0 + wn * 32 + ni * 8 + (lane & 3) * 2;
            float2 v0 = {acc[mi][ni][0] * sc, acc[mi][ni][1] * sc};
            float2 v1 = {acc[mi][ni][2] * sc, acc[mi][ni][3] * sc};
            *(float2*)&S[(size_t)rb * Nn + col]       = v0;
            *(float2*)&S[(size_t)(rb + 8) * Nn + col] = v1;
        }
    }
}

// ---------------------------------------------------------------------------
// Kernel 3: row softmax (fp32 in, bf16 probs out)
// ---------------------------------------------------------------------------
__device__ __forceinline__ float warp_max(float v) {
    #pragma unroll
    for (int o = 16; o > 0; o >>= 1) v = fmaxf(v, __shfl_xor_sync(0xffffffffu, v, o));
    return v;
}
__device__ __forceinline__ float warp_sum(float v) {
    #pragma unroll
    for (int o = 16; o > 0; o >>= 1) v += __shfl_xor_sync(0xffffffffu, v, o);
    return v;
}

__global__ __launch_bounds__(256) void softmax_kernel()
{
    int i = blockIdx.x, b = blockIdx.y;
    const float* row = g_S + ((size_t)b * Nn + i) * Nn;
    __nv_bfloat16* Prow = g_P + ((size_t)b * Nn + i) * Nn;
    int tid = threadIdx.x;
    int lane = tid & 31, w = tid >> 5;

    float4 v[4];
    float mx = -1e30f;
    #pragma unroll
    for (int c = 0; c < 4; ++c) {
        v[c] = *(const float4*)&row[(c * 256 + tid) * 4];
        mx = fmaxf(mx, fmaxf(fmaxf(v[c].x, v[c].y), fmaxf(v[c].z, v[c].w)));
    }

    __shared__ float redm[8], reds[8];
    mx = warp_max(mx);
    if (lane == 0) redm[w] = mx;
    __syncthreads();
    float m = redm[0];
    #pragma unroll
    for (int k = 1; k < 8; ++k) m = fmaxf(m, redm[k]);

    float s = 0.f;
    #pragma unroll
    for (int c = 0; c < 4; ++c) {
        v[c].x = __expf(v[c].x - m); v[c].y = __expf(v[c].y - m);
        v[c].z = __expf(v[c].z - m); v[c].w = __expf(v[c].w - m);
        s += v[c].x + v[c].y + v[c].z + v[c].w;
    }
    s = warp_sum(s);
    if (lane == 0) reds[w] = s;
    __syncthreads();
    float tot = 0.f;
    #pragma unroll
    for (int k = 0; k < 8; ++k) tot += reds[k];
    float inv = __frcp_rn(tot);

    #pragma unroll
    for (int c = 0; c < 4; ++c) {
        __nv_bfloat162 p[2];
        p[0] = __floats2bfloat162_rn(v[c].x * inv, v[c].y * inv);
        p[1] = __floats2bfloat162_rn(v[c].z * inv, v[c].w * inv);
        *(uint2*)&Prow[(c * 256 + tid) * 4] = *(uint2*)p;
    }
}

// ---------------------------------------------------------------------------
// Kernel 4: context via HMMA. D[c,i] = sum_j Vb[c,j] P[i,j]; out = x + D
// grid: (N/128 i, C/128 c, B), block 256
// ---------------------------------------------------------------------------
__global__ __launch_bounds__(256) void context_mma(
    const float* __restrict__ x, float* __restrict__ out)
{
    int b = blockIdx.z;
    int i0 = blockIdx.x * 128, c0 = blockIdx.y * 128;
    const __nv_bfloat16* A  = g_Vb + (size_t)b * Cc * Nn + (size_t)c0 * Nn;  // m = c
    const __nv_bfloat16* Bg = g_P  + (size_t)b * Nn * Nn + (size_t)i0 * Nn;  // n = i

    float acc[4][4][4] = {};
    gemm_bf16<Nn, Nn, Nn / 32>(A, Bg, acc);

    int lane = threadIdx.x & 31, wid = threadIdx.x >> 5;
    int wm = wid & 1, wn = wid >> 1;

    #pragma unroll
    for (int mi = 0; mi < 4; ++mi) {
        int crow = c0 + wm * 64 + mi * 16 + (lane >> 2);
        #pragma unroll
        for (int ni = 0; ni < 4; ++ni) {
            int icol = i0 + wn * 32 + ni * 8 + (lane & 3) * 2;
            size_t a0 = ((size_t)b * Cc + crow) * Nn + icol;
            size_t a1 = a0 + (size_t)8 * Nn;
            float2 x0 = *(const float2*)&x[a0];
            float2 x1 = *(const float2*)&x[a1];
            float2 o0v = {acc[mi][ni][0] + x0.x, acc[mi][ni][1] + x0.y};
            float2 o1v = {acc[mi][ni][2] + x1.x, acc[mi][ni][3] + x1.y};
            *(float2*)&out[a0] = o0v;
            *(float2*)&out[a1] = o1v;
        }
    }
}

// ---------------------------------------------------------------------------
extern "C" void kernel_launch(void* const* d_in, const int* in_sizes, int n_in,
                              void* d_out, int out_size)
{
    const float* x  = (const float*)d_in[0];
    const float* Wq = (const float*)d_in[1];
    const float* bq = (const float*)d_in[2];
    const float* Wk = (const float*)d_in[3];
    const float* bk = (const float*)d_in[4];
    const float* Wv = (const float*)d_in[5];
    const float* bv = (const float*)d_in[6];
    float* out = (float*)d_out;

    dim3 blk(256);

    dim3 g_qkv(Nn / 128, Cc / 128, Bz * 3);
    qkv_kernel<<<g_qkv, blk>>>(x, Wq, bq, Wk, bk, Wv, bv);

    dim3 g_sc(Nn / 128, Nn / 128, Bz);
    scores_mma<<<g_sc, blk>>>();

    dim3 g_sm(Nn, Bz);
    softmax_kernel<<<g_sm, blk>>>();

    dim3 g_ctx(Nn / 128, Cc / 128, Bz);
    context_mma<<<g_ctx, blk>>>(x, out);
}

// round 5
// speedup vs baseline: 4.6847x; 1.1520x over previous
#include <cuda_runtime.h>
#include <cuda_bf16.h>
#include <cstdint>
#include <math.h>

#define Bz 4
#define Cc 256
#define Nn 4096
#define BM 64
#define BN 128
#define NSTEP (Nn / BN)   // 32

// ---------------- device scratch -------------------------------------------
__device__ __nv_bfloat16 g_Qt[(size_t)Bz * Nn * Cc];  // Q^T  [b][i][c]
__device__ __nv_bfloat16 g_Kt[(size_t)Bz * Nn * Cc];  // K^T  [b][j][c]
__device__ __nv_bfloat16 g_Vb[(size_t)Bz * Cc * Nn];  // V    [b][c][j]

// ---------------- PTX helpers (plain sm_103-safe) ---------------------------
__device__ __forceinline__ uint32_t smem_u32(const void* p) {
    uint32_t a;
    asm("{ .reg .u64 t; cvta.to.shared.u64 t, %1; cvt.u32.u64 %0, t; }"
        : "=r"(a) : "l"(p));
    return a;
}
__device__ __forceinline__ void ldsm4(uint32_t* r, uint32_t a) {
    asm volatile("ldmatrix.sync.aligned.m8n8.x4.shared.b16 {%0,%1,%2,%3}, [%4];"
                 : "=r"(r[0]), "=r"(r[1]), "=r"(r[2]), "=r"(r[3]) : "r"(a));
}
__device__ __forceinline__ void mma16816(float* c, const uint32_t* a,
                                         uint32_t b0, uint32_t b1) {
    asm volatile(
        "mma.sync.aligned.m16n8k16.row.col.f32.bf16.bf16.f32 "
        "{%0,%1,%2,%3}, {%4,%5,%6,%7}, {%8,%9}, {%0,%1,%2,%3};"
        : "+f"(c[0]), "+f"(c[1]), "+f"(c[2]), "+f"(c[3])
        : "r"(a[0]), "r"(a[1]), "r"(a[2]), "r"(a[3]), "r"(b0), "r"(b1));
}
#define CP_ASYNC16(dst, src) \
    asm volatile("cp.async.cg.shared.global [%0], [%1], 16;" :: "r"(dst), "l"(src))
#define CP_COMMIT() asm volatile("cp.async.commit_group;" ::: "memory")
#define CP_WAIT1()  asm volatile("cp.async.wait_group 1;" ::: "memory")

// smem strides (bf16 elems); 528B and 272B rows -> ldmatrix conflict-free
#define SQK 264
#define SVP 136
#define OFF_Q 0
#define OFF_K (64 * SQK)            // after Q (64 rows)
#define OFF_V (OFF_K + 128 * SQK)   // after K (128 rows)
#define OFF_P (OFF_V + 256 * SVP)   // after V (256 rows)
#define SMEM_BYTES ((OFF_P + 64 * SVP) * 2)   // 188416 B

// ---------------------------------------------------------------------------
// Kernel 1: QKV projection (fp32 SIMT) -> bf16 operand layouts (unchanged)
// ---------------------------------------------------------------------------
#define BK 16
#define LDA 132

__global__ __launch_bounds__(256) void qkv_kernel(
    const float* __restrict__ x,
    const float* __restrict__ Wq, const float* __restrict__ bq,
    const float* __restrict__ Wk, const float* __restrict__ bk,
    const float* __restrict__ Wv, const float* __restrict__ bv)
{
    int m = blockIdx.z % 3;
    int b = blockIdx.z / 3;
    const float* W    = (m == 0) ? Wq : (m == 1) ? Wk : Wv;
    const float* bias = (m == 0) ? bq : (m == 1) ? bk : bv;
    const float* X = x + (size_t)b * Cc * Nn;

    int o0 = blockIdx.y * 128;
    int n0 = blockIdx.x * 128;

    __shared__ float As[BK][LDA];
    __shared__ float Bs[BK][LDA];

    int tid = threadIdx.x;
    int tx = tid & 15, ty = tid >> 4;
    float acc[8][8] = {};

    for (int k0 = 0; k0 < Cc; k0 += BK) {
        #pragma unroll
        for (int it = 0; it < 2; ++it) {
            int idx = tid + it * 256;
            int o = idx >> 2, k4 = idx & 3;
            float4 v = *(const float4*)&W[(o0 + o) * Cc + k0 + k4 * 4];
            As[k4 * 4 + 0][o] = v.x; As[k4 * 4 + 1][o] = v.y;
            As[k4 * 4 + 2][o] = v.z; As[k4 * 4 + 3][o] = v.w;
        }
        #pragma unroll
        for (int it = 0; it < 2; ++it) {
            int idx = tid + it * 256;
            int k = idx >> 5, n4 = idx & 31;
            *(float4*)&Bs[k][n4 * 4] = *(const float4*)&X[(k0 + k) * Nn + n0 + n4 * 4];
        }
        __syncthreads();
        #pragma unroll
        for (int k = 0; k < BK; ++k) {
            float a[8], bb[8];
            *(float4*)&a[0]  = *(const float4*)&As[k][ty * 8];
            *(float4*)&a[4]  = *(const float4*)&As[k][ty * 8 + 4];
            *(float4*)&bb[0] = *(const float4*)&Bs[k][tx * 8];
            *(float4*)&bb[4] = *(const float4*)&Bs[k][tx * 8 + 4];
            #pragma unroll
            for (int r = 0; r < 8; ++r)
                #pragma unroll
                for (int c = 0; c < 8; ++c)
                    acc[r][c] += a[r] * bb[c];
        }
        __syncthreads();
    }

    float bias8[8];
    #pragma unroll
    for (int r = 0; r < 8; ++r) bias8[r] = bias[o0 + ty * 8 + r];

    if (m == 2) {
        __nv_bfloat16* Vb = g_Vb + (size_t)b * Cc * Nn;
        #pragma unroll
        for (int r = 0; r < 8; ++r) {
            __nv_bfloat162 p[4];
            #pragma unroll
            for (int e = 0; e < 4; ++e)
                p[e] = __floats2bfloat162_rn(acc[r][2 * e] + bias8[r],
                                             acc[r][2 * e + 1] + bias8[r]);
            *(uint4*)&Vb[(size_t)(o0 + ty * 8 + r) * Nn + n0 + tx * 8] = *(uint4*)p;
        }
    } else {
        __nv_bfloat16* T = ((m == 0) ? g_Qt : g_Kt) + (size_t)b * Nn * Cc;
        #pragma unroll
        for (int c = 0; c < 8; ++c) {
            __nv_bfloat162 p[4];
            #pragma unroll
            for (int e = 0; e < 4; ++e)
                p[e] = __floats2bfloat162_rn(acc[2 * e][c] + bias8[2 * e],
                                             acc[2 * e + 1][c] + bias8[2 * e + 1]);
            *(uint4*)&T[(size_t)(n0 + tx * 8 + c) * Cc + o0 + ty * 8] = *(uint4*)p;
        }
    }
}

// ---------------------------------------------------------------------------
// Kernel 2: fused flash attention. grid (Nn/BM, Bz), 256 threads.
// ---------------------------------------------------------------------------
__device__ __forceinline__ void load_K(const __nv_bfloat16* Kg,
                                       __nv_bfloat16* Ks, int j0, int tid) {
    #pragma unroll
    for (int h = 0; h < 16; ++h) {
        int q = tid + h * 256;
        int r = q >> 5, cb = q & 31;
        CP_ASYNC16(smem_u32(Ks + r * SQK + cb * 8),
                   Kg + (size_t)(j0 + r) * Cc + cb * 8);
    }
    CP_COMMIT();
}
__device__ __forceinline__ void load_V(const __nv_bfloat16* Vg,
                                       __nv_bfloat16* Vs, int j0, int tid) {
    #pragma unroll
    for (int h = 0; h < 16; ++h) {
        int q = tid + h * 256;
        int r = q >> 4, cb = q & 15;
        CP_ASYNC16(smem_u32(Vs + r * SVP + cb * 8),
                   Vg + (size_t)r * Nn + j0 + cb * 8);
    }
    CP_COMMIT();
}

__global__ __launch_bounds__(256, 1) void flash_kernel(
    const float* __restrict__ x, float* __restrict__ out)
{
    extern __shared__ __nv_bfloat16 sm[];
    __shared__ float sm_mx[128], sm_sum[128];

    const int tid = threadIdx.x;
    const int lane = tid & 31, wid = tid >> 5;
    const int wm = wid & 3, wn = wid >> 2;
    const int b = blockIdx.y;
    const int i0 = blockIdx.x * BM;

    const __nv_bfloat16* Qg = g_Qt + (size_t)b * Nn * Cc + (size_t)i0 * Cc;
    const __nv_bfloat16* Kg = g_Kt + (size_t)b * Nn * Cc;
    const __nv_bfloat16* Vg = g_Vb + (size_t)b * Cc * Nn;

    __nv_bfloat16* Qs = sm + OFF_Q;
    __nv_bfloat16* Ks = sm + OFF_K;
    __nv_bfloat16* Vs = sm + OFF_V;
    __nv_bfloat16* Ps = sm + OFF_P;

    // prologue: {Q + K(0)} as group 0, {V(0)} as group 1
    #pragma unroll
    for (int h = 0; h < 8; ++h) {
        int q = tid + h * 256;
        int r = q >> 5, cb = q & 31;
        CP_ASYNC16(smem_u32(Qs + r * SQK + cb * 8), Qg + (size_t)r * Cc + cb * 8);
    }
    #pragma unroll
    for (int h = 0; h < 16; ++h) {
        int q = tid + h * 256;
        int r = q >> 5, cb = q & 31;
        CP_ASYNC16(smem_u32(Ks + r * SQK + cb * 8), Kg + (size_t)r * Cc + cb * 8);
    }
    CP_COMMIT();
    load_V(Vg, Vs, 0, tid);

    // ldmatrix lane addressing
    const int aA_row  = wm * 16 + (lane & 15);
    const int aA_koff = (lane >> 4) * 8;
    const int bK_row  = wn * 64  + (lane & 7) + ((lane >> 4) << 3);
    const int bV_row  = wn * 128 + (lane & 7) + ((lane >> 4) << 3);
    const int b_koff  = ((lane >> 3) & 1) * 8;
    const int r0l = wm * 16 + (lane >> 2);      // tile-local row (and r0l+8)

    float dacc[16][4] = {};
    float m0 = -1e30f, m1 = -1e30f, l0 = 0.f, l1 = 0.f;

    #pragma unroll 1
    for (int t = 0; t < NSTEP; ++t) {
        CP_WAIT1();                 // K(t) (and Q on t=0) complete
        __syncthreads();            // visible to all

        // ---- S = (Q @ K^T) * scale  (warp tile 16 x 64)
        float sacc[8][4] = {};
        #pragma unroll
        for (int ks = 0; ks < 16; ++ks) {
            uint32_t af[4];
            ldsm4(af, smem_u32(Qs + aA_row * SQK + ks * 16 + aA_koff));
            uint32_t bf[4][4];
            #pragma unroll
            for (int nh = 0; nh < 4; ++nh)
                ldsm4(bf[nh], smem_u32(Ks + (bK_row + nh * 16) * SQK + ks * 16 + b_koff));
            #pragma unroll
            for (int ni = 0; ni < 8; ++ni)
                mma16816(sacc[ni], af, bf[ni >> 1][(ni & 1) * 2],
                         bf[ni >> 1][(ni & 1) * 2 + 1]);
        }

        // ---- online softmax: tile row max (within warp, then across wn pair)
        float tmx0 = -1e30f, tmx1 = -1e30f;
        #pragma unroll
        for (int ni = 0; ni < 8; ++ni) {
            sacc[ni][0] *= 0.0625f; sacc[ni][1] *= 0.0625f;
            sacc[ni][2] *= 0.0625f; sacc[ni][3] *= 0.0625f;
            tmx0 = fmaxf(tmx0, fmaxf(sacc[ni][0], sacc[ni][1]));
            tmx1 = fmaxf(tmx1, fmaxf(sacc[ni][2], sacc[ni][3]));
        }
        tmx0 = fmaxf(tmx0, __shfl_xor_sync(0xffffffffu, tmx0, 1));
        tmx0 = fmaxf(tmx0, __shfl_xor_sync(0xffffffffu, tmx0, 2));
        tmx1 = fmaxf(tmx1, __shfl_xor_sync(0xffffffffu, tmx1, 1));
        tmx1 = fmaxf(tmx1, __shfl_xor_sync(0xffffffffu, tmx1, 2));
        if ((lane & 3) == 0) {
            sm_mx[wn * 64 + r0l]     = tmx0;
            sm_mx[wn * 64 + r0l + 8] = tmx1;
        }
        __syncthreads();            // mx visible; K smem free

        load_K(Kg, Ks, ((t + 1) & (NSTEP - 1)) * BN, tid);   // prefetch K(t+1)

        float mn0 = fmaxf(m0, fmaxf(sm_mx[r0l],     sm_mx[64 + r0l]));
        float mn1 = fmaxf(m1, fmaxf(sm_mx[r0l + 8], sm_mx[64 + r0l + 8]));
        float al0 = __expf(m0 - mn0);
        float al1 = __expf(m1 - mn1);
        m0 = mn0; m1 = mn1;

        float ts0 = 0.f, ts1 = 0.f;
        uint32_t pp[8][2];
        #pragma unroll
        for (int ni = 0; ni < 8; ++ni) {
            float p0 = __expf(sacc[ni][0] - mn0);
            float p1 = __expf(sacc[ni][1] - mn0);
            float p2 = __expf(sacc[ni][2] - mn1);
            float p3 = __expf(sacc[ni][3] - mn1);
            ts0 += p0 + p1; ts1 += p2 + p3;
            __nv_bfloat162 q0 = __floats2bfloat162_rn(p0, p1);
            __nv_bfloat162 q1 = __floats2bfloat162_rn(p2, p3);
            pp[ni][0] = *(uint32_t*)&q0;
            pp[ni][1] = *(uint32_t*)&q1;
        }
        ts0 += __shfl_xor_sync(0xffffffffu, ts0, 1);
        ts0 += __shfl_xor_sync(0xffffffffu, ts0, 2);
        ts1 += __shfl_xor_sync(0xffffffffu, ts1, 1);
        ts1 += __shfl_xor_sync(0xffffffffu, ts1, 2);
        if ((lane & 3) == 0) {
            sm_sum[wn * 64 + r0l]     = ts0;
            sm_sum[wn * 64 + r0l + 8] = ts1;
        }
        __syncthreads();

        l0 = l0 * al0 + sm_sum[r0l]     + sm_sum[64 + r0l];
        l1 = l1 * al1 + sm_sum[r0l + 8] + sm_sum[64 + r0l + 8];

        #pragma unroll
        for (int ni = 0; ni < 16; ++ni) {
            dacc[ni][0] *= al0; dacc[ni][1] *= al0;
            dacc[ni][2] *= al1; dacc[ni][3] *= al1;
        }

        // store P tile (bf16) to smem
        {
            int pc = wn * 64 + (lane & 3) * 2;
            #pragma unroll
            for (int ni = 0; ni < 8; ++ni) {
                *(uint32_t*)(Ps + r0l * SVP + pc + ni * 8)       = pp[ni][0];
                *(uint32_t*)(Ps + (r0l + 8) * SVP + pc + ni * 8) = pp[ni][1];
            }
        }

        CP_WAIT1();                 // V(t) complete (K(t+1) may remain)
        __syncthreads();            // P visible + all threads waited V

        // ---- D += P @ V^T  (warp tile 16 x 128, k = 128)
        #pragma unroll
        for (int ks = 0; ks < 8; ++ks) {
            uint32_t af[4];
            ldsm4(af, smem_u32(Ps + aA_row * SVP + ks * 16 + aA_koff));
            uint32_t bf[8][4];
            #pragma unroll
            for (int nh = 0; nh < 8; ++nh)
                ldsm4(bf[nh], smem_u32(Vs + (bV_row + nh * 16) * SVP + ks * 16 + b_koff));
            #pragma unroll
            for (int ni = 0; ni < 16; ++ni)
                mma16816(dacc[ni], af, bf[ni >> 1][(ni & 1) * 2],
                         bf[ni >> 1][(ni & 1) * 2 + 1]);
        }
        __syncthreads();            // all done reading V & P

        load_V(Vg, Vs, ((t + 1) & (NSTEP - 1)) * BN, tid);   // prefetch V(t+1)
    }

    // ---- epilogue: out = x + D / l
    float inv0 = 1.f / l0, inv1 = 1.f / l1;
    int gi = i0 + r0l;
    #pragma unroll
    for (int ni = 0; ni < 16; ++ni) {
        int c = wn * 128 + ni * 8 + (lane & 3) * 2;
        size_t b0a = ((size_t)b * Cc + c) * Nn;
        size_t b1a = b0a + Nn;
        out[b0a + gi]     = x[b0a + gi]     + dacc[ni][0] * inv0;
        out[b1a + gi]     = x[b1a + gi]     + dacc[ni][1] * inv0;
        out[b0a + gi + 8] = x[b0a + gi + 8] + dacc[ni][2] * inv1;
        out[b1a + gi + 8] = x[b1a + gi + 8] + dacc[ni][3] * inv1;
    }
}

// ---------------------------------------------------------------------------
extern "C" void kernel_launch(void* const* d_in, const int* in_sizes, int n_in,
                              void* d_out, int out_size)
{
    const float* x  = (const float*)d_in[0];
    const float* Wq = (const float*)d_in[1];
    const float* bq = (const float*)d_in[2];
    const float* Wk = (const float*)d_in[3];
    const float* bk = (const float*)d_in[4];
    const float* Wv = (const float*)d_in[5];
    const float* bv = (const float*)d_in[6];
    float* out = (float*)d_out;

    cudaFuncSetAttribute(flash_kernel,
                         cudaFuncAttributeMaxDynamicSharedMemorySize, SMEM_BYTES);

    dim3 blk(256);
    dim3 g_qkv(Nn / 128, Cc / 128, Bz * 3);
    qkv_kernel<<<g_qkv, blk>>>(x, Wq, bq, Wk, bk, Wv, bv);

    dim3 g_fl(Nn / BM, Bz);
    flash_kernel<<<g_fl, blk, SMEM_BYTES>>>(x, out);
}